// round 11
// baseline (speedup 1.0000x reference)
#include <cuda_runtime.h>
#include <math.h>
#include <stdint.h>

#define D_MODEL 1024
#define L_SEQ   2048
#define BATCH   4
#define NHEADS  16
#define ROWS    (BATCH * L_SEQ)   /* 8192 */

/* ---------------- scratch (static device globals; no allocations) -------- */
__device__ float g_xn  [ (size_t)ROWS * D_MODEL ];
__device__ float g_qkv [ (size_t)ROWS * 3 * D_MODEL ];
__device__ float g_attn[ (size_t)ROWS * D_MODEL ];

/* ---------------- helpers ------------------------------------------------ */
__device__ __forceinline__ unsigned smaddr(const void* p) {
    return (unsigned)__cvta_generic_to_shared(p);
}
__device__ __forceinline__ void cp16(unsigned dst, const void* src) {
    asm volatile("cp.async.cg.shared.global [%0], [%1], 16;\n"
                 :: "r"(dst), "l"(src));
}
__device__ __forceinline__ void mma_tf32(
    float& c0, float& c1, float& c2, float& c3,
    unsigned a0, unsigned a1, unsigned a2, unsigned a3,
    unsigned b0, unsigned b1)
{
    asm volatile(
        "mma.sync.aligned.m16n8k8.row.col.f32.tf32.tf32.f32 "
        "{%0,%1,%2,%3},{%4,%5,%6,%7},{%8,%9},{%0,%1,%2,%3};"
        : "+f"(c0), "+f"(c1), "+f"(c2), "+f"(c3)
        : "r"(a0), "r"(a1), "r"(a2), "r"(a3), "r"(b0), "r"(b1));
}

/* ---------------- LayerNorm ---------------------------------------------- */
__global__ __launch_bounds__(256) void ln_kernel(
    const float* __restrict__ x, const float* __restrict__ g,
    const float* __restrict__ b, float* __restrict__ out)
{
    int row = blockIdx.x;
    int t   = threadIdx.x;
    const float4* xr = (const float4*)(x + (size_t)row * D_MODEL);
    float4 v = xr[t];
    float s  = v.x + v.y + v.z + v.w;
    float sq = v.x*v.x + v.y*v.y + v.z*v.z + v.w*v.w;

    __shared__ float red0[8], red1[8];
    #pragma unroll
    for (int off = 16; off > 0; off >>= 1) {
        s  += __shfl_down_sync(0xffffffffu, s,  off);
        sq += __shfl_down_sync(0xffffffffu, sq, off);
    }
    int warp = t >> 5, lane = t & 31;
    if (lane == 0) { red0[warp] = s; red1[warp] = sq; }
    __syncthreads();
    if (t < 32) {
        float s2 = (t < 8) ? red0[t] : 0.f;
        float q2 = (t < 8) ? red1[t] : 0.f;
        #pragma unroll
        for (int off = 4; off > 0; off >>= 1) {
            s2 += __shfl_down_sync(0xffffffffu, s2, off);
            q2 += __shfl_down_sync(0xffffffffu, q2, off);
        }
        if (t == 0) {
            float mu  = s2 * (1.0f / D_MODEL);
            float var = q2 * (1.0f / D_MODEL) - mu * mu;
            red0[0] = mu;
            red1[0] = rsqrtf(var + 1e-5f);
        }
    }
    __syncthreads();
    float mu = red0[0], rstd = red1[0];
    float4 gv = ((const float4*)g)[t];
    float4 bv = ((const float4*)b)[t];
    float4 o;
    o.x = (v.x - mu) * rstd * gv.x + bv.x;
    o.y = (v.y - mu) * rstd * gv.y + bv.y;
    o.z = (v.z - mu) * rstd * gv.z + bv.z;
    o.w = (v.w - mu) * rstd * gv.w + bv.w;
    ((float4*)(out + (size_t)row * D_MODEL))[t] = o;
}

/* ---------------- tf32 tensor-core GEMM, 128x128x16, 4-stage cp.async ----
   4 warps, warp tile 64x64 (2x2 grid): per 8-K step 32 LDS vs 32 MMA.
   As [m=128][k=16] stride 20, Bs [k=16][n=128] stride 132.
   ONE __syncthreads per K-chunk; wait_group 2 keeps two stages in flight. */
#define ASTR 20
#define BSTR 132
#define ASZ  (128 * ASTR)   /* 2560 floats */
#define BSZ  (16 * BSTR)    /* 2112 floats */
#define NST  4

template<bool RES>
__global__ __launch_bounds__(128, 2) void mma_gemm(
    const float* __restrict__ A, const float* __restrict__ B,
    const float* __restrict__ bias, const float* __restrict__ res,
    float* __restrict__ C, int M, int N, int K)
{
    extern __shared__ float sh[];
    float* As = sh;                  /* [NST][ASZ] */
    float* Bs = sh + NST * ASZ;      /* [NST][BSZ] */

    int tid  = threadIdx.x, warp = tid >> 5, lane = tid & 31;
    int g    = lane >> 2,   t4   = lane & 3;
    int wm   = (warp >> 1) * 64, wn = (warp & 1) * 64;
    int brow = blockIdx.y * 128, bcol = blockIdx.x * 128;

    float acc[4][8][4];
    #pragma unroll
    for (int i = 0; i < 4; i++)
        #pragma unroll
        for (int j = 0; j < 8; j++)
            #pragma unroll
            for (int c = 0; c < 4; c++) acc[i][j][c] = 0.f;

    /* loaders (128 thr): A row=tid, 4x float4; B krow=tid>>3, n16=(tid&7)*16 */
    int ar = tid;
    int bk = tid >> 3, bn = (tid & 7) * 16;
    const float* Ag = A + (size_t)(brow + ar) * K;
    const float* Bg = B + (size_t)bk * N + bcol + bn;
    unsigned aSm[NST], bSm[NST];
    #pragma unroll
    for (int s = 0; s < NST; s++) {
        aSm[s] = smaddr(As + s * ASZ + ar * ASTR);
        bSm[s] = smaddr(Bs + s * BSZ + bk * BSTR + bn);
    }

    int nit = K / 16;

    /* prefetch stages 0..2 */
    #pragma unroll
    for (int s = 0; s < NST - 1; s++) {
        int k0 = s * 16;
        #pragma unroll
        for (int q = 0; q < 4; q++) {
            cp16(aSm[s] + q * 16, Ag + k0 + q * 4);
            cp16(bSm[s] + q * 16, Bg + (size_t)k0 * N + q * 4);
        }
        asm volatile("cp.async.commit_group;");
    }

    for (int it = 0; it < nit; it++) {
        asm volatile("cp.async.wait_group 2;");
        __syncthreads();

        int ld = it + NST - 1;
        if (ld < nit) {
            int s  = ld & (NST - 1);
            int k0 = ld * 16;
            #pragma unroll
            for (int q = 0; q < 4; q++) {
                cp16(aSm[s] + q * 16, Ag + k0 + q * 4);
                cp16(bSm[s] + q * 16, Bg + (size_t)k0 * N + q * 4);
            }
        }
        asm volatile("cp.async.commit_group;");

        const float* as = As + (it & (NST - 1)) * ASZ;
        const float* bs = Bs + (it & (NST - 1)) * BSZ;
        #pragma unroll
        for (int ks = 0; ks < 2; ks++) {
            int kc = ks * 8;
            unsigned a[4][4];
            #pragma unroll
            for (int i = 0; i < 4; i++) {
                int r0 = wm + 16 * i + g;
                a[i][0] = __float_as_uint(as[(r0    ) * ASTR + kc + t4    ]);
                a[i][1] = __float_as_uint(as[(r0 + 8) * ASTR + kc + t4    ]);
                a[i][2] = __float_as_uint(as[(r0    ) * ASTR + kc + t4 + 4]);
                a[i][3] = __float_as_uint(as[(r0 + 8) * ASTR + kc + t4 + 4]);
            }
            #pragma unroll
            for (int j = 0; j < 8; j++) {
                unsigned b0 = __float_as_uint(bs[(kc + t4    ) * BSTR + wn + 8*j + g]);
                unsigned b1 = __float_as_uint(bs[(kc + t4 + 4) * BSTR + wn + 8*j + g]);
                #pragma unroll
                for (int i = 0; i < 4; i++)
                    mma_tf32(acc[i][j][0], acc[i][j][1], acc[i][j][2], acc[i][j][3],
                             a[i][0], a[i][1], a[i][2], a[i][3], b0, b1);
            }
        }
    }

    /* epilogue: bias (+ residual) fused, float2 stores */
    #pragma unroll
    for (int j = 0; j < 8; j++) {
        int col = bcol + wn + 8 * j + 2 * t4;
        float2 bi = *(const float2*)&bias[col];
        #pragma unroll
        for (int i = 0; i < 4; i++) {
            int r0 = brow + wm + 16 * i + g;
            float2 v0 = { acc[i][j][0] + bi.x, acc[i][j][1] + bi.y };
            float2 v1 = { acc[i][j][2] + bi.x, acc[i][j][3] + bi.y };
            if (RES) {
                float2 ra = *(const float2*)&res[(size_t)(r0    ) * N + col];
                float2 rb = *(const float2*)&res[(size_t)(r0 + 8) * N + col];
                v0.x += ra.x; v0.y += ra.y;
                v1.x += rb.x; v1.y += rb.y;
            }
            *(float2*)&C[(size_t)(r0    ) * N + col] = v0;
            *(float2*)&C[(size_t)(r0 + 8) * N + col] = v1;
        }
    }
}

/* ---------------- flash attention (unchanged from R8/best) --------------- */
#define QS 68

__global__ __launch_bounds__(256, 2) void flash_mma(
    const float* __restrict__ qkv, float* __restrict__ out)
{
    extern __shared__ float sm[];
    float* Qs = sm;
    float* Ks = Qs + 128 * QS;
    float* Vs = Ks + 64 * QS;
    float* Ps = Vs + 64 * QS;

    int qt = blockIdx.x, h = blockIdx.y, b = blockIdx.z;
    int tid = threadIdx.x, warp = tid >> 5, lane = tid & 31;
    int g = lane >> 2, t4 = lane & 3;
    const float scale = 0.125f;
    const float* base = qkv + (size_t)b * L_SEQ * 3072 + h * 64;

    for (int idx = tid; idx < 128 * 16; idx += 256) {
        int r = idx >> 4, c4 = (idx & 15) * 4;
        float4 q = *(const float4*)(base + (size_t)(qt * 128 + r) * 3072 + c4);
        float* d = &Qs[r * QS + c4];
        d[0] = q.x * scale; d[1] = q.y * scale;
        d[2] = q.z * scale; d[3] = q.w * scale;
    }

    float ofr[8][4];
    #pragma unroll
    for (int j = 0; j < 8; j++)
        #pragma unroll
        for (int c = 0; c < 4; c++) ofr[j][c] = 0.f;
    float m_lo = -INFINITY, m_hi = -INFINITY, l_lo = 0.f, l_hi = 0.f;

    int rlo = warp * 16 + g;

    for (int kt = 0; kt < L_SEQ / 64; kt++) {
        __syncthreads();
        for (int idx = tid; idx < 64 * 16; idx += 256) {
            int r = idx >> 4, c4 = (idx & 15) * 4;
            const float* kp = base + 1024 + (size_t)(kt * 64 + r) * 3072 + c4;
            float4 kv = *(const float4*)kp;
            float4 vv = *(const float4*)(kp + 1024);
            *(float4*)&Ks[r * QS + c4] = kv;
            *(float4*)&Vs[r * QS + c4] = vv;
        }
        __syncthreads();

        float sfr[8][4];
        #pragma unroll
        for (int j = 0; j < 8; j++)
            #pragma unroll
            for (int c = 0; c < 4; c++) sfr[j][c] = 0.f;
        #pragma unroll
        for (int ks = 0; ks < 8; ks++) {
            int kc = ks * 8;
            unsigned a0 = __float_as_uint(Qs[(rlo    ) * QS + kc + t4    ]);
            unsigned a1 = __float_as_uint(Qs[(rlo + 8) * QS + kc + t4    ]);
            unsigned a2 = __float_as_uint(Qs[(rlo    ) * QS + kc + t4 + 4]);
            unsigned a3 = __float_as_uint(Qs[(rlo + 8) * QS + kc + t4 + 4]);
            #pragma unroll
            for (int j = 0; j < 8; j++) {
                unsigned b0 = __float_as_uint(Ks[(8*j + g) * QS + kc + t4    ]);
                unsigned b1 = __float_as_uint(Ks[(8*j + g) * QS + kc + t4 + 4]);
                mma_tf32(sfr[j][0], sfr[j][1], sfr[j][2], sfr[j][3],
                         a0, a1, a2, a3, b0, b1);
            }
        }

        float mx_lo = -INFINITY, mx_hi = -INFINITY;
        #pragma unroll
        for (int j = 0; j < 8; j++) {
            mx_lo = fmaxf(mx_lo, fmaxf(sfr[j][0], sfr[j][1]));
            mx_hi = fmaxf(mx_hi, fmaxf(sfr[j][2], sfr[j][3]));
        }
        mx_lo = fmaxf(mx_lo, __shfl_xor_sync(0xffffffffu, mx_lo, 1));
        mx_lo = fmaxf(mx_lo, __shfl_xor_sync(0xffffffffu, mx_lo, 2));
        mx_hi = fmaxf(mx_hi, __shfl_xor_sync(0xffffffffu, mx_hi, 1));
        mx_hi = fmaxf(mx_hi, __shfl_xor_sync(0xffffffffu, mx_hi, 2));
        float mn_lo = fmaxf(m_lo, mx_lo), mn_hi = fmaxf(m_hi, mx_hi);
        float sc_lo = __expf(m_lo - mn_lo), sc_hi = __expf(m_hi - mn_hi);
        float sum_lo = 0.f, sum_hi = 0.f;
        #pragma unroll
        for (int j = 0; j < 8; j++) {
            float p0 = __expf(sfr[j][0] - mn_lo);
            float p1 = __expf(sfr[j][1] - mn_lo);
            float p2 = __expf(sfr[j][2] - mn_hi);
            float p3 = __expf(sfr[j][3] - mn_hi);
            sum_lo += p0 + p1; sum_hi += p2 + p3;
            float2* plo = (float2*)&Ps[(rlo    ) * QS + 8*j + 2*t4];
            float2* phi = (float2*)&Ps[(rlo + 8) * QS + 8*j + 2*t4];
            *plo = make_float2(p0, p1);
            *phi = make_float2(p2, p3);
        }
        sum_lo += __shfl_xor_sync(0xffffffffu, sum_lo, 1);
        sum_lo += __shfl_xor_sync(0xffffffffu, sum_lo, 2);
        sum_hi += __shfl_xor_sync(0xffffffffu, sum_hi, 1);
        sum_hi += __shfl_xor_sync(0xffffffffu, sum_hi, 2);
        l_lo = l_lo * sc_lo + sum_lo; m_lo = mn_lo;
        l_hi = l_hi * sc_hi + sum_hi; m_hi = mn_hi;
        #pragma unroll
        for (int j = 0; j < 8; j++) {
            ofr[j][0] *= sc_lo; ofr[j][1] *= sc_lo;
            ofr[j][2] *= sc_hi; ofr[j][3] *= sc_hi;
        }
        __syncwarp();

        #pragma unroll
        for (int ks = 0; ks < 8; ks++) {
            int kc = ks * 8;
            unsigned a0 = __float_as_uint(Ps[(rlo    ) * QS + kc + t4    ]);
            unsigned a1 = __float_as_uint(Ps[(rlo + 8) * QS + kc + t4    ]);
            unsigned a2 = __float_as_uint(Ps[(rlo    ) * QS + kc + t4 + 4]);
            unsigned a3 = __float_as_uint(Ps[(rlo + 8) * QS + kc + t4 + 4]);
            #pragma unroll
            for (int j = 0; j < 8; j++) {
                unsigned b0 = __float_as_uint(Vs[(kc + t4    ) * QS + 8*j + g]);
                unsigned b1 = __float_as_uint(Vs[(kc + t4 + 4) * QS + 8*j + g]);
                mma_tf32(ofr[j][0], ofr[j][1], ofr[j][2], ofr[j][3],
                         a0, a1, a2, a3, b0, b1);
            }
        }
    }

    float inv_lo = 1.f / l_lo, inv_hi = 1.f / l_hi;
    int row_lo = b * L_SEQ + qt * 128 + warp * 16 + g;
    #pragma unroll
    for (int j = 0; j < 8; j++) {
        int col = h * 64 + 8 * j + 2 * t4;
        float2 v0 = make_float2(ofr[j][0] * inv_lo, ofr[j][1] * inv_lo);
        float2 v1 = make_float2(ofr[j][2] * inv_hi, ofr[j][3] * inv_hi);
        *(float2*)&out[(size_t)(row_lo    ) * D_MODEL + col] = v0;
        *(float2*)&out[(size_t)(row_lo + 8) * D_MODEL + col] = v1;
    }
}

/* ---------------- launcher ----------------------------------------------- */
extern "C" void kernel_launch(void* const* d_in, const int* in_sizes, int n_in,
                              void* d_out, int out_size)
{
    const float* x     = (const float*)d_in[0];
    const float* w_qkv = (const float*)d_in[1];
    const float* b_qkv = (const float*)d_in[2];
    const float* w_fc  = (const float*)d_in[3];
    const float* b_fc  = (const float*)d_in[4];
    const float* ln_g  = (const float*)d_in[5];
    const float* ln_b  = (const float*)d_in[6];
    float* out = (float*)d_out;

    float *xn, *qkvp, *attnp;
    cudaGetSymbolAddress((void**)&xn,    g_xn);
    cudaGetSymbolAddress((void**)&qkvp,  g_qkv);
    cudaGetSymbolAddress((void**)&attnp, g_attn);

    /* 1. LayerNorm */
    ln_kernel<<<ROWS, 256>>>(x, ln_g, ln_b, xn);

    /* 2. QKV GEMM: [8192,1024] @ [1024,3072] + bias */
    int gsm = NST * (ASZ + BSZ) * (int)sizeof(float);   /* 74752 B */
    cudaFuncSetAttribute(mma_gemm<false>,
                         cudaFuncAttributeMaxDynamicSharedMemorySize, gsm);
    cudaFuncSetAttribute(mma_gemm<true>,
                         cudaFuncAttributeMaxDynamicSharedMemorySize, gsm);
    dim3 g1(3 * D_MODEL / 128, ROWS / 128);
    mma_gemm<false><<<g1, 128, gsm>>>(xn, w_qkv, b_qkv, nullptr, qkvp,
                                      ROWS, 3 * D_MODEL, D_MODEL);

    /* 3. Flash attention */
    int smem_bytes = 384 * QS * (int)sizeof(float);   /* 104448 B */
    cudaFuncSetAttribute(flash_mma,
                         cudaFuncAttributeMaxDynamicSharedMemorySize, smem_bytes);
    flash_mma<<<dim3(L_SEQ / 128, NHEADS, BATCH), 256, smem_bytes>>>(qkvp, attnp);

    /* 4. Projection GEMM + bias + residual */
    dim3 g2(D_MODEL / 128, ROWS / 128);
    mma_gemm<true><<<g2, 128, gsm>>>(attnp, w_fc, b_fc, x, out,
                                     ROWS, D_MODEL, D_MODEL);
}

// round 14
// speedup vs baseline: 1.0986x; 1.0986x over previous
#include <cuda_runtime.h>
#include <math.h>
#include <stdint.h>

#define D_MODEL 1024
#define L_SEQ   2048
#define BATCH   4
#define NHEADS  16
#define ROWS    (BATCH * L_SEQ)   /* 8192 */

/* ---------------- scratch (static device globals; no allocations) -------- */
__device__ float g_xn  [ (size_t)ROWS * D_MODEL ];
__device__ float g_qkv [ (size_t)ROWS * 3 * D_MODEL ];
__device__ float g_attn[ (size_t)ROWS * D_MODEL ];

/* ---------------- helpers ------------------------------------------------ */
__device__ __forceinline__ unsigned smaddr(const void* p) {
    return (unsigned)__cvta_generic_to_shared(p);
}
__device__ __forceinline__ void cp16(unsigned dst, const void* src) {
    asm volatile("cp.async.cg.shared.global [%0], [%1], 16;\n"
                 :: "r"(dst), "l"(src));
}
__device__ __forceinline__ float ex2(float x) {
    float r; asm("ex2.approx.ftz.f32 %0, %1;" : "=f"(r) : "f"(x)); return r;
}
__device__ __forceinline__ void mma_tf32(
    float& c0, float& c1, float& c2, float& c3,
    unsigned a0, unsigned a1, unsigned a2, unsigned a3,
    unsigned b0, unsigned b1)
{
    asm volatile(
        "mma.sync.aligned.m16n8k8.row.col.f32.tf32.tf32.f32 "
        "{%0,%1,%2,%3},{%4,%5,%6,%7},{%8,%9},{%0,%1,%2,%3};"
        : "+f"(c0), "+f"(c1), "+f"(c2), "+f"(c3)
        : "r"(a0), "r"(a1), "r"(a2), "r"(a3), "r"(b0), "r"(b1));
}

/* ---------------- LayerNorm ---------------------------------------------- */
__global__ __launch_bounds__(256) void ln_kernel(
    const float* __restrict__ x, const float* __restrict__ g,
    const float* __restrict__ b, float* __restrict__ out)
{
    int row = blockIdx.x;
    int t   = threadIdx.x;
    const float4* xr = (const float4*)(x + (size_t)row * D_MODEL);
    float4 v = xr[t];
    float s  = v.x + v.y + v.z + v.w;
    float sq = v.x*v.x + v.y*v.y + v.z*v.z + v.w*v.w;

    __shared__ float red0[8], red1[8];
    #pragma unroll
    for (int off = 16; off > 0; off >>= 1) {
        s  += __shfl_down_sync(0xffffffffu, s,  off);
        sq += __shfl_down_sync(0xffffffffu, sq, off);
    }
    int warp = t >> 5, lane = t & 31;
    if (lane == 0) { red0[warp] = s; red1[warp] = sq; }
    __syncthreads();
    if (t < 32) {
        float s2 = (t < 8) ? red0[t] : 0.f;
        float q2 = (t < 8) ? red1[t] : 0.f;
        #pragma unroll
        for (int off = 4; off > 0; off >>= 1) {
            s2 += __shfl_down_sync(0xffffffffu, s2, off);
            q2 += __shfl_down_sync(0xffffffffu, q2, off);
        }
        if (t == 0) {
            float mu  = s2 * (1.0f / D_MODEL);
            float var = q2 * (1.0f / D_MODEL) - mu * mu;
            red0[0] = mu;
            red1[0] = rsqrtf(var + 1e-5f);
        }
    }
    __syncthreads();
    float mu = red0[0], rstd = red1[0];
    float4 gv = ((const float4*)g)[t];
    float4 bv = ((const float4*)b)[t];
    float4 o;
    o.x = (v.x - mu) * rstd * gv.x + bv.x;
    o.y = (v.y - mu) * rstd * gv.y + bv.y;
    o.z = (v.z - mu) * rstd * gv.z + bv.z;
    o.w = (v.w - mu) * rstd * gv.w + bv.w;
    ((float4*)(out + (size_t)row * D_MODEL))[t] = o;
}

/* ---------------- tf32 tensor-core GEMM (R8-proven, unchanged) -----------
   128x128x16 tile, 4-stage cp.async ring, 8 warps 4x2, warp tile 32x64. -- */
#define ASTR 20
#define BSTR 132
#define ASZ  (128 * ASTR)   /* 2560 floats */
#define BSZ  (16 * BSTR)    /* 2112 floats */
#define NST  4

template<bool RES>
__global__ __launch_bounds__(256, 2) void mma_gemm(
    const float* __restrict__ A, const float* __restrict__ B,
    const float* __restrict__ bias, const float* __restrict__ res,
    float* __restrict__ C, int M, int N, int K)
{
    extern __shared__ float sh[];
    float* As = sh;                  /* [NST][ASZ] */
    float* Bs = sh + NST * ASZ;      /* [NST][BSZ] */

    int tid  = threadIdx.x, warp = tid >> 5, lane = tid & 31;
    int g    = lane >> 2,   t4   = lane & 3;
    int wm   = (warp >> 1) * 32, wn = (warp & 1) * 64;
    int brow = blockIdx.y * 128, bcol = blockIdx.x * 128;

    float acc[2][8][4];
    #pragma unroll
    for (int i = 0; i < 2; i++)
        #pragma unroll
        for (int j = 0; j < 8; j++)
            #pragma unroll
            for (int c = 0; c < 4; c++) acc[i][j][c] = 0.f;

    int ar = tid >> 1, ak = (tid & 1) * 8;
    int bk = tid >> 4, bn = (tid & 15) * 8;
    const float* Ag = A + (size_t)(brow + ar) * K + ak;
    const float* Bg = B + (size_t)bk * N + bcol + bn;
    unsigned aSm[NST], bSm[NST];
    #pragma unroll
    for (int s = 0; s < NST; s++) {
        aSm[s] = smaddr(As + s * ASZ + ar * ASTR + ak);
        bSm[s] = smaddr(Bs + s * BSZ + bk * BSTR + bn);
    }

    int nit = K / 16;

    #pragma unroll
    for (int s = 0; s < NST - 1; s++) {
        int k0 = s * 16;
        cp16(aSm[s],      Ag + k0);
        cp16(aSm[s] + 16, Ag + k0 + 4);
        cp16(bSm[s],      Bg + (size_t)k0 * N);
        cp16(bSm[s] + 16, Bg + (size_t)k0 * N + 4);
        asm volatile("cp.async.commit_group;");
    }

    for (int it = 0; it < nit; it++) {
        asm volatile("cp.async.wait_group 2;");
        __syncthreads();

        int ld = it + NST - 1;
        if (ld < nit) {
            int s  = ld & (NST - 1);
            int k0 = ld * 16;
            cp16(aSm[s],      Ag + k0);
            cp16(aSm[s] + 16, Ag + k0 + 4);
            cp16(bSm[s],      Bg + (size_t)k0 * N);
            cp16(bSm[s] + 16, Bg + (size_t)k0 * N + 4);
        }
        asm volatile("cp.async.commit_group;");

        const float* as = As + (it & (NST - 1)) * ASZ;
        const float* bs = Bs + (it & (NST - 1)) * BSZ;
        #pragma unroll
        for (int ks = 0; ks < 2; ks++) {
            int kc = ks * 8;
            unsigned a[2][4];
            #pragma unroll
            for (int i = 0; i < 2; i++) {
                int r0 = wm + 16 * i + g;
                a[i][0] = __float_as_uint(as[(r0    ) * ASTR + kc + t4    ]);
                a[i][1] = __float_as_uint(as[(r0 + 8) * ASTR + kc + t4    ]);
                a[i][2] = __float_as_uint(as[(r0    ) * ASTR + kc + t4 + 4]);
                a[i][3] = __float_as_uint(as[(r0 + 8) * ASTR + kc + t4 + 4]);
            }
            #pragma unroll
            for (int j = 0; j < 8; j++) {
                unsigned b0 = __float_as_uint(bs[(kc + t4    ) * BSTR + wn + 8*j + g]);
                unsigned b1 = __float_as_uint(bs[(kc + t4 + 4) * BSTR + wn + 8*j + g]);
                mma_tf32(acc[0][j][0], acc[0][j][1], acc[0][j][2], acc[0][j][3],
                         a[0][0], a[0][1], a[0][2], a[0][3], b0, b1);
                mma_tf32(acc[1][j][0], acc[1][j][1], acc[1][j][2], acc[1][j][3],
                         a[1][0], a[1][1], a[1][2], a[1][3], b0, b1);
            }
        }
    }

    #pragma unroll
    for (int j = 0; j < 8; j++) {
        int col = bcol + wn + 8 * j + 2 * t4;
        float2 bi = *(const float2*)&bias[col];
        #pragma unroll
        for (int i = 0; i < 2; i++) {
            int r0 = brow + wm + 16 * i + g;
            float2 v0 = { acc[i][j][0] + bi.x, acc[i][j][1] + bi.y };
            float2 v1 = { acc[i][j][2] + bi.x, acc[i][j][3] + bi.y };
            if (RES) {
                float2 ra = *(const float2*)&res[(size_t)(r0    ) * N + col];
                float2 rb = *(const float2*)&res[(size_t)(r0 + 8) * N + col];
                v0.x += ra.x; v0.y += ra.y;
                v1.x += rb.x; v1.y += rb.y;
            }
            *(float2*)&C[(size_t)(r0    ) * N + col] = v0;
            *(float2*)&C[(size_t)(r0 + 8) * N + col] = v1;
        }
    }
}

/* ---------------- flash attention v2 -------------------------------------
   BR=128, BC=64, 8 warps. Q in registers (pre-scaled by 0.125*log2e),
   K/V double-buffered via cp.async (stage kt+1 issued during kt compute),
   ONE __syncthreads per kt, exp2-domain softmax.
   smem: K[2] 64xQS, V[2] 64xQS, P 128xQS  = 384*QS floats (104448 B). --- */
#define QS 68

__global__ __launch_bounds__(256, 2) void flash_mma(
    const float* __restrict__ qkv, float* __restrict__ out)
{
    extern __shared__ float sm[];
    float* K0 = sm;
    float* K1 = sm + 64 * QS;
    float* V0 = sm + 128 * QS;
    float* V1 = sm + 192 * QS;
    float* Ps = sm + 256 * QS;      /* also Q staging before the loop */

    int qt = blockIdx.x, h = blockIdx.y, b = blockIdx.z;
    int tid = threadIdx.x, warp = tid >> 5, lane = tid & 31;
    int g = lane >> 2, t4 = lane & 3;
    const float SC = 0.125f * 1.4426950408889634f;  /* scale * log2(e) */
    const float* base = qkv + (size_t)b * L_SEQ * 3072 + h * 64;

    /* per-thread load slots for K/V tiles (4 x 16B each) */
    int lr = tid >> 2;               /* row 0..63  */
    int lc = (tid & 3) * 16;         /* col 0,16,32,48 */
    const float* kg = base + 1024 + (size_t)lr * 3072 + lc;
    unsigned kS[2][4], vS[2][4];
    #pragma unroll
    for (int q = 0; q < 4; q++) {
        kS[0][q] = smaddr(K0 + lr * QS + lc + q * 4);
        kS[1][q] = smaddr(K1 + lr * QS + lc + q * 4);
        vS[0][q] = smaddr(V0 + lr * QS + lc + q * 4);
        vS[1][q] = smaddr(V1 + lr * QS + lc + q * 4);
    }

    /* stage Q into Ps (coalesced), issue K0/V0 prefetch */
    for (int idx = tid; idx < 128 * 16; idx += 256) {
        int r = idx >> 4, c4 = (idx & 15) * 4;
        float4 q = *(const float4*)(base + (size_t)(qt * 128 + r) * 3072 + c4);
        *(float4*)&Ps[r * QS + c4] = q;
    }
    {
        const float* src = kg;       /* kt = 0 */
        #pragma unroll
        for (int q = 0; q < 4; q++) {
            cp16(kS[0][q], src + q * 4);
            cp16(vS[0][q], src + 1024 + q * 4);
        }
        asm volatile("cp.async.commit_group;");
    }
    __syncthreads();

    /* Q fragments into registers, pre-scaled */
    int rlo = warp * 16 + g;
    float qf[8][4];
    #pragma unroll
    for (int ks = 0; ks < 8; ks++) {
        int kc = ks * 8;
        qf[ks][0] = Ps[(rlo    ) * QS + kc + t4    ] * SC;
        qf[ks][1] = Ps[(rlo + 8) * QS + kc + t4    ] * SC;
        qf[ks][2] = Ps[(rlo    ) * QS + kc + t4 + 4] * SC;
        qf[ks][3] = Ps[(rlo + 8) * QS + kc + t4 + 4] * SC;
    }

    float ofr[8][4];
    #pragma unroll
    for (int j = 0; j < 8; j++)
        #pragma unroll
        for (int c = 0; c < 4; c++) ofr[j][c] = 0.f;
    float m_lo = -INFINITY, m_hi = -INFINITY, l_lo = 0.f, l_hi = 0.f;

    for (int kt = 0; kt < L_SEQ / 64; kt++) {
        asm volatile("cp.async.wait_group 0;");
        __syncthreads();   /* stage kt visible everywhere; buffers (kt+1)&1 free */

        if (kt + 1 < L_SEQ / 64) {
            int nb = (kt + 1) & 1;
            const float* src = kg + (size_t)(kt + 1) * 64 * 3072;
            #pragma unroll
            for (int q = 0; q < 4; q++) {
                cp16(kS[nb][q], src + q * 4);
                cp16(vS[nb][q], src + 1024 + q * 4);
            }
            asm volatile("cp.async.commit_group;");
        } else {
            asm volatile("cp.async.commit_group;");
        }

        const float* Ks = (kt & 1) ? K1 : K0;
        const float* Vs = (kt & 1) ? V1 : V0;

        /* S = Q @ K^T (log2 domain) */
        float sfr[8][4];
        #pragma unroll
        for (int j = 0; j < 8; j++)
            #pragma unroll
            for (int c = 0; c < 4; c++) sfr[j][c] = 0.f;
        #pragma unroll
        for (int ks = 0; ks < 8; ks++) {
            int kc = ks * 8;
            unsigned a0 = __float_as_uint(qf[ks][0]);
            unsigned a1 = __float_as_uint(qf[ks][1]);
            unsigned a2 = __float_as_uint(qf[ks][2]);
            unsigned a3 = __float_as_uint(qf[ks][3]);
            #pragma unroll
            for (int j = 0; j < 8; j++) {
                unsigned b0 = __float_as_uint(Ks[(8*j + g) * QS + kc + t4    ]);
                unsigned b1 = __float_as_uint(Ks[(8*j + g) * QS + kc + t4 + 4]);
                mma_tf32(sfr[j][0], sfr[j][1], sfr[j][2], sfr[j][3],
                         a0, a1, a2, a3, b0, b1);
            }
        }

        /* warp-local online softmax, exp2 domain */
        float mx_lo = -INFINITY, mx_hi = -INFINITY;
        #pragma unroll
        for (int j = 0; j < 8; j++) {
            mx_lo = fmaxf(mx_lo, fmaxf(sfr[j][0], sfr[j][1]));
            mx_hi = fmaxf(mx_hi, fmaxf(sfr[j][2], sfr[j][3]));
        }
        mx_lo = fmaxf(mx_lo, __shfl_xor_sync(0xffffffffu, mx_lo, 1));
        mx_lo = fmaxf(mx_lo, __shfl_xor_sync(0xffffffffu, mx_lo, 2));
        mx_hi = fmaxf(mx_hi, __shfl_xor_sync(0xffffffffu, mx_hi, 1));
        mx_hi = fmaxf(mx_hi, __shfl_xor_sync(0xffffffffu, mx_hi, 2));
        float mn_lo = fmaxf(m_lo, mx_lo), mn_hi = fmaxf(m_hi, mx_hi);
        float sc_lo = ex2(m_lo - mn_lo), sc_hi = ex2(m_hi - mn_hi);
        float sum_lo = 0.f, sum_hi = 0.f;
        #pragma unroll
        for (int j = 0; j < 8; j++) {
            float p0 = ex2(sfr[j][0] - mn_lo);
            float p1 = ex2(sfr[j][1] - mn_lo);
            float p2 = ex2(sfr[j][2] - mn_hi);
            float p3 = ex2(sfr[j][3] - mn_hi);
            sum_lo += p0 + p1; sum_hi += p2 + p3;
            float2* plo = (float2*)&Ps[(rlo    ) * QS + 8*j + 2*t4];
            float2* phi = (float2*)&Ps[(rlo + 8) * QS + 8*j + 2*t4];
            *plo = make_float2(p0, p1);
            *phi = make_float2(p2, p3);
        }
        sum_lo += __shfl_xor_sync(0xffffffffu, sum_lo, 1);
        sum_lo += __shfl_xor_sync(0xffffffffu, sum_lo, 2);
        sum_hi += __shfl_xor_sync(0xffffffffu, sum_hi, 1);
        sum_hi += __shfl_xor_sync(0xffffffffu, sum_hi, 2);
        l_lo = l_lo * sc_lo + sum_lo; m_lo = mn_lo;
        l_hi = l_hi * sc_hi + sum_hi; m_hi = mn_hi;
        #pragma unroll
        for (int j = 0; j < 8; j++) {
            ofr[j][0] *= sc_lo; ofr[j][1] *= sc_lo;
            ofr[j][2] *= sc_hi; ofr[j][3] *= sc_hi;
        }
        __syncwarp();   /* warp-private P rows visible within warp */

        /* O += P @ V */
        #pragma unroll
        for (int ks = 0; ks < 8; ks++) {
            int kc = ks * 8;
            unsigned a0 = __float_as_uint(Ps[(rlo    ) * QS + kc + t4    ]);
            unsigned a1 = __float_as_uint(Ps[(rlo + 8) * QS + kc + t4    ]);
            unsigned a2 = __float_as_uint(Ps[(rlo    ) * QS + kc + t4 + 4]);
            unsigned a3 = __float_as_uint(Ps[(rlo + 8) * QS + kc + t4 + 4]);
            #pragma unroll
            for (int j = 0; j < 8; j++) {
                unsigned b0 = __float_as_uint(Vs[(kc + t4    ) * QS + 8*j + g]);
                unsigned b1 = __float_as_uint(Vs[(kc + t4 + 4) * QS + 8*j + g]);
                mma_tf32(ofr[j][0], ofr[j][1], ofr[j][2], ofr[j][3],
                         a0, a1, a2, a3, b0, b1);
            }
        }
    }

    float inv_lo = 1.f / l_lo, inv_hi = 1.f / l_hi;
    int row_lo = b * L_SEQ + qt * 128 + warp * 16 + g;
    #pragma unroll
    for (int j = 0; j < 8; j++) {
        int col = h * 64 + 8 * j + 2 * t4;
        float2 v0 = make_float2(ofr[j][0] * inv_lo, ofr[j][1] * inv_lo);
        float2 v1 = make_float2(ofr[j][2] * inv_hi, ofr[j][3] * inv_hi);
        *(float2*)&out[(size_t)(row_lo    ) * D_MODEL + col] = v0;
        *(float2*)&out[(size_t)(row_lo + 8) * D_MODEL + col] = v1;
    }
}

/* ---------------- launcher ----------------------------------------------- */
extern "C" void kernel_launch(void* const* d_in, const int* in_sizes, int n_in,
                              void* d_out, int out_size)
{
    const float* x     = (const float*)d_in[0];
    const float* w_qkv = (const float*)d_in[1];
    const float* b_qkv = (const float*)d_in[2];
    const float* w_fc  = (const float*)d_in[3];
    const float* b_fc  = (const float*)d_in[4];
    const float* ln_g  = (const float*)d_in[5];
    const float* ln_b  = (const float*)d_in[6];
    float* out = (float*)d_out;

    float *xn, *qkvp, *attnp;
    cudaGetSymbolAddress((void**)&xn,    g_xn);
    cudaGetSymbolAddress((void**)&qkvp,  g_qkv);
    cudaGetSymbolAddress((void**)&attnp, g_attn);

    /* 1. LayerNorm */
    ln_kernel<<<ROWS, 256>>>(x, ln_g, ln_b, xn);

    /* 2. QKV GEMM: [8192,1024] @ [1024,3072] + bias */
    int gsm = NST * (ASZ + BSZ) * (int)sizeof(float);   /* 74752 B */
    cudaFuncSetAttribute(mma_gemm<false>,
                         cudaFuncAttributeMaxDynamicSharedMemorySize, gsm);
    cudaFuncSetAttribute(mma_gemm<true>,
                         cudaFuncAttributeMaxDynamicSharedMemorySize, gsm);
    dim3 g1(3 * D_MODEL / 128, ROWS / 128);
    mma_gemm<false><<<g1, 256, gsm>>>(xn, w_qkv, b_qkv, nullptr, qkvp,
                                      ROWS, 3 * D_MODEL, D_MODEL);

    /* 3. Flash attention */
    int smem_bytes = 384 * QS * (int)sizeof(float);   /* 104448 B */
    cudaFuncSetAttribute(flash_mma,
                         cudaFuncAttributeMaxDynamicSharedMemorySize, smem_bytes);
    flash_mma<<<dim3(L_SEQ / 128, NHEADS, BATCH), 256, smem_bytes>>>(qkvp, attnp);

    /* 4. Projection GEMM + bias + residual */
    dim3 g2(D_MODEL / 128, ROWS / 128);
    mma_gemm<true><<<g2, 256, gsm>>>(attnp, w_fc, b_fc, x, out,
                                     ROWS, D_MODEL, D_MODEL);
}